// round 12
// baseline (speedup 1.0000x reference)
#include <cuda_runtime.h>

// LossMIDU: mean over 4-connected components of the tanh(x)>0 mask of
//   sum(tanh(x) in comp) / (N+1 - count(comp)).
// Two-level CCL:
//   k_tiles : per 16x128 tile — local union-find + accumulation in SMEM,
//             export (sum,cnt) per local root (plain store), global parent
//             entries for local roots + boundary pixels, per-tile root list.
//   k_mergev/k_mergeh : global unions on tile-boundary edges only.
//   k_reloc : fold non-root acc entries into their global root.
//   k_final : reduce over root lists, last block writes output.

static constexpr int E        = 4096;
static constexpr int NPIX     = E * E;
static constexpr int WPR      = E / 32;            // 128 mask words per row
static constexpr int TW       = 128;               // tile width
static constexpr int TH       = 16;                // tile height
static constexpr int TPIX     = TW * TH;           // 2048
static constexpr int TWORDS   = TPIX / 32;         // 64 words per tile
static constexpr int TILES_X  = E / TW;            // 32
static constexpr int TILES_Y  = E / TH;            // 256
static constexpr int NTILES   = TILES_X * TILES_Y; // 8192
static constexpr int MAXR_T   = TPIX / 2;          // 1024 max comps/tile

__device__ int      g_parent[NPIX];
__device__ float2   g_acc[NPIX];
__device__ unsigned g_mask[NPIX / 32];
__device__ int      g_rlist[NTILES * MAXR_T];
__device__ int      g_rootcnt[NTILES];
__device__ double   g_total;
__device__ double   g_ncomp;
__device__ unsigned g_done;

// tanh for v > 0 via MUFU (verified rel_err 0.0 in rounds 5/7/9/11).
__device__ __forceinline__ float tanh_pos(float v) {
    float e = __expf(-2.0f * v);
    return __fdividef(1.0f - e, 1.0f + e);
}

// ---------- global union-find (links strictly decreasing) ----------
__device__ __forceinline__ int find_root(int i) {
    int p = g_parent[i];
    if (p == i) return i;
    while (true) {
        int gp = g_parent[p];
        if (gp == p) return p;
        g_parent[i] = gp;
        i = p; p = gp;
    }
}
__device__ __forceinline__ void unite(int a, int b) {
    int ra = find_root(a), rb = find_root(b);
    while (ra != rb) {
        if (ra > rb) { int t = ra; ra = rb; rb = t; }
        int old = atomicCAS(&g_parent[rb], rb, ra);
        if (old == rb) return;
        rb = find_root(old);
    }
}

// ---------- local (smem) union-find ----------
__device__ __forceinline__ int lfind(int* sp, int i) {
    int p = sp[i];
    if (p == i) return i;
    while (true) {
        int gp = sp[p];
        if (gp == p) return p;
        sp[i] = gp;
        i = p; p = gp;
    }
}
__device__ __forceinline__ void lunite(int* sp, int a, int b) {
    int ra = lfind(sp, a), rb = lfind(sp, b);
    while (ra != rb) {
        if (ra > rb) { int t = ra; ra = rb; rb = t; }
        int old = atomicCAS(&sp[rb], rb, ra);
        if (old == rb) return;
        rb = lfind(sp, old);
    }
}

// skewed smem index for the x tile (bank-conflict-free word-major reads)
__device__ __forceinline__ int sxi(int word, int j) {
    return word * 32 + ((j + word) & 31);
}

__global__ void __launch_bounds__(TWORDS) k_tiles(const float* __restrict__ x) {
    __shared__ float    sx[TPIX];
    __shared__ int      sparent[TPIX];
    __shared__ float    ssum[TPIX];
    __shared__ int      scnt[TPIX];
    __shared__ unsigned smask[TWORDS];
    __shared__ int      s_nroots;

    int bid = blockIdx.x;
    int tc  = bid % TILES_X;
    int tr  = bid / TILES_X;
    int t   = threadIdx.x;               // 0..63 = word id
    int r   = t >> 2;                    // tile row 0..15
    int wc  = t & 3;                     // word-in-row 0..3

    if (t == 0) s_nroots = 0;
    if (bid == 0 && t == 0) { g_total = 0.0; g_ncomp = 0.0; g_done = 0u; }

    // --- load x tile, coalesced float4, into skewed smem ---
    {
        const float4* x4 = reinterpret_cast<const float4*>(x);
        #pragma unroll
        for (int pass = 0; pass < 8; pass++) {
            int f4id = pass * TWORDS + t;          // 0..511
            int row  = f4id >> 5;                  // tile row
            int c4   = f4id & 31;                  // float4 col in tile
            int grow = tr * TH + row;
            float4 v = x4[((size_t)grow * E + tc * TW) / 4 + c4];
            int col  = c4 * 4;
            int w0   = row * 4 + (col >> 5);
            sx[sxi(w0,  col        & 31)] = v.x;
            sx[sxi(w0, (col + 1)   & 31)] = v.y;
            sx[sxi(w0, (col + 2)   & 31)] = v.z;
            sx[sxi(w0, (col + 3)   & 31)] = v.w;
        }
    }
    __syncthreads();

    // --- build mask word for my word ---
    unsigned m = 0;
    #pragma unroll
    for (int j = 0; j < 32; j++)
        m |= (unsigned)(sx[sxi(t, j)] > 0.0f) << j;
    smask[t] = m;
    {
        int grow = tr * TH + r;
        g_mask[grow * WPR + tc * 4 + wc] = m;
    }
    __syncthreads();

    // --- local parent init: run start within tile row; zero acc ---
    int lbase = r * TW + wc * 32;
    {
        int leftstart = 0;                           // tile col where left-chained run begins
        for (int p = wc - 1; p >= 0; p--) {
            unsigned wp = smask[r * 4 + p];
            if (wp != 0xffffffffu) { leftstart = p * 32 + (32 - __clz(~wp)); break; }
        }
        #pragma unroll
        for (int j = 0; j < 32; j++) {
            int l = lbase + j;
            ssum[l] = 0.0f; scnt[l] = 0;
            if ((m >> j) & 1u) {
                unsigned below = (j == 0) ? 0u : ((~m) & ((1u << j) - 1u));
                int rs = below ? (wc * 32 + (32 - __clz(below))) : leftstart;
                sparent[l] = r * TW + rs;
            }
        }
    }
    __syncthreads();

    // --- local vertical unions (rows 1..TH-1), dedup at overlap-run starts ---
    if (r > 0) {
        unsigned up = smask[t - 4];
        unsigned ov = m & up;
        if (ov) {
            unsigned carry = 0;
            if (wc > 0) carry = (smask[t - 1] >> 31) & (smask[t - 5] >> 31);
            unsigned starts = ov & ~((ov << 1) | carry);
            while (starts) {
                int b = __ffs(starts) - 1;
                starts &= starts - 1;
                lunite(sparent, lbase + b, lbase + b - TW);
            }
        }
    }
    __syncthreads();

    // --- accumulate per tile-local horizontal run into local root ---
    {
        unsigned carryL = wc ? ((smask[t - 1] >> 31) & 1u) : 0u;
        unsigned hstarts = m & ~((m << 1) | carryL);
        while (hstarts) {
            int b = __ffs(hstarts) - 1;
            hstarts &= hstarts - 1;
            int col = wc * 32 + b;
            float s = 0.0f; int len = 0;
            int c = col;
            while (c < TW) {
                unsigned wm = smask[r * 4 + (c >> 5)];
                if (!((wm >> (c & 31)) & 1u)) break;
                s += tanh_pos(sx[sxi(r * 4 + (c >> 5), c & 31)]);
                len++; c++;
            }
            int lr = lfind(sparent, r * TW + col);
            atomicAdd(&ssum[lr], s);
            atomicAdd(&scnt[lr], len);
        }
    }
    __syncthreads();

    // --- export: roots (acc + parent + root list) and boundary parents ---
    {
        #pragma unroll
        for (int j = 0; j < 32; j++) {
            int  l  = lbase + j;
            int  rr = r;
            int  cc = wc * 32 + j;
            int  g  = (tr * TH + rr) * E + tc * TW + cc;
            bool masked = (m >> j) & 1u;
            if (scnt[l] > 0) {                       // local root
                __stcs(&g_acc[g], make_float2(ssum[l], (float)scnt[l]));
                g_parent[g] = g;
                int slot = atomicAdd(&s_nroots, 1);
                g_rlist[bid * MAXR_T + slot] = g;
            } else if (masked &&
                       (rr == 0 || rr == TH - 1 || cc == 0 || cc == TW - 1)) {
                int lr = lfind(sparent, l);
                int gr = (tr * TH + lr / TW) * E + tc * TW + (lr % TW);
                g_parent[g] = gr;                    // points to local root (< g)
            }
        }
    }
    __syncthreads();
    if (t == 0) g_rootcnt[bid] = s_nroots;
}

// Global vertical unions along horizontal tile boundaries (rows = k*TH),
// word-based dedup — identical logic to the verified full-grid k_merge.
__global__ void __launch_bounds__(WPR) k_mergev() {
    int row  = (blockIdx.x + 1) * TH;
    int wcol = threadIdx.x;
    int widx = row * WPR + wcol;
    unsigned wcm = g_mask[widx];
    unsigned wum = g_mask[widx - WPR];
    unsigned ov  = wcm & wum;
    if (!ov) return;

    int lane = threadIdx.x & 31;
    unsigned cl = __shfl_up_sync(0xffffffffu, wcm, 1);
    unsigned ul = __shfl_up_sync(0xffffffffu, wum, 1);
    unsigned carry = 0;
    if (wcol > 0) {
        if (lane == 0) {
            cl = g_mask[widx - 1];
            ul = g_mask[widx - 1 - WPR];
        }
        carry = (cl >> 31) & (ul >> 31) & 1u;
    }
    unsigned starts = ov & ~((ov << 1) | carry);

    int base = row * E + (wcol << 5);
    while (starts) {
        int b = __ffs(starts) - 1;
        starts &= starts - 1;
        unite(base + b, base + b - E);
    }
}

// Global horizontal unions across vertical tile boundaries (cols = k*TW).
__global__ void k_mergeh() {
    int idx = blockIdx.x * blockDim.x + threadIdx.x;
    if (idx >= E * (TILES_X - 1)) return;
    int row = idx / (TILES_X - 1);
    int cb  = idx % (TILES_X - 1);
    int c   = (cb + 1) * TW;
    unsigned wR = g_mask[row * WPR + (c >> 5)];
    unsigned wL = g_mask[row * WPR + (c >> 5) - 1];
    if ((wR & 1u) && (wL >> 31)) {
        int p = row * E + c;
        unite(p, p - 1);
    }
}

// Fold non-root acc entries into their global root. Roots are fixed after the
// merge kernels, so an entry with find(i)!=i can never receive concurrent adds.
__global__ void __launch_bounds__(128) k_reloc() {
    int bid = blockIdx.x;
    int n   = g_rootcnt[bid];
    for (int k = threadIdx.x; k < n; k += blockDim.x) {
        int i = g_rlist[bid * MAXR_T + k];
        int r = find_root(i);
        if (r != i) {
            float2 v = g_acc[i];
            atomicAdd(&g_acc[r], v);               // sm_90+ vector red
            __stcs(&g_acc[i], make_float2(0.f, 0.f));
        }
    }
}

// Reduce over root lists; zero consumed entries; last block writes output.
__global__ void __launch_bounds__(128) k_final(float* __restrict__ out) {
    int bid = blockIdx.x;
    int n   = g_rootcnt[bid];
    const float np1 = (float)(NPIX + 1);
    double t = 0.0, c = 0.0;
    for (int k = threadIdx.x; k < n; k += blockDim.x) {
        int i = g_rlist[bid * MAXR_T + k];
        int r = find_root(i);
        if (r == i) {
            float2 a = g_acc[i];
            t += (double)(a.x / (np1 - a.y));      // fp32 divide like reference
            c += 1.0;
            __stcs(&g_acc[i], make_float2(0.f, 0.f));
        }
    }
    #pragma unroll
    for (int off = 16; off; off >>= 1) {
        t += __shfl_down_sync(0xffffffffu, t, off);
        c += __shfl_down_sync(0xffffffffu, c, off);
    }
    __shared__ double st[4], sc[4];
    int lane = threadIdx.x & 31;
    int w    = threadIdx.x >> 5;
    if (lane == 0) { st[w] = t; sc[w] = c; }
    __syncthreads();
    if (w == 0) {
        t = (lane < 4) ? st[lane] : 0.0;
        c = (lane < 4) ? sc[lane] : 0.0;
        #pragma unroll
        for (int off = 2; off; off >>= 1) {
            t += __shfl_down_sync(0xffffffffu, t, off);
            c += __shfl_down_sync(0xffffffffu, c, off);
        }
        if (lane == 0) {
            atomicAdd(&g_total, t);
            atomicAdd(&g_ncomp, c);
            __threadfence();
            unsigned ticket = atomicAdd(&g_done, 1u);
            if (ticket == gridDim.x - 1) {
                double tt = *((volatile double*)&g_total);
                double nc = *((volatile double*)&g_ncomp);
                out[0] = (nc > 0.0) ? (float)(tt / nc) : 0.0f;
            }
        }
    }
}

extern "C" void kernel_launch(void* const* d_in, const int* in_sizes, int n_in,
                              void* d_out, int out_size) {
    const float* x   = (const float*)d_in[0];
    float*       out = (float*)d_out;

    k_tiles <<<NTILES, TWORDS>>>(x);
    k_mergev<<<TILES_Y - 1, WPR>>>();
    k_mergeh<<<(E * (TILES_X - 1)) / 128, 128>>>();
    k_reloc <<<NTILES, 128>>>();
    k_final <<<NTILES, 128>>>(out);
}

// round 13
// speedup vs baseline: 1.4890x; 1.4890x over previous
#include <cuda_runtime.h>

// LossMIDU: mean over 4-connected components of the tanh(x)>0 mask of
//   sum(tanh(x) in comp) / (N+1 - count(comp)).
// Flat run-based union-find CCL:
//   k_init : parent = row-run start (warp scan); per-run (tanh-sum, len)
//            plain-stored at the run start; bitmask emitted.
//   k_merge: vertical CAS unions from mask words (dedup at overlap starts).
//   k_reloc: per run start (from mask): root? push to block-aggregated root
//            list : one vector atomicAdd of its (s,len) into the root.
//   k_final: gather over compact root list; ticketed write of the answer.

static constexpr int E      = 4096;
static constexpr int NPIX   = E * E;
static constexpr int WORDS  = NPIX / 32;
static constexpr int WPR    = E / 32;          // mask words per row = 128
static constexpr int MAXR   = NPIX / 2;

__device__ int      g_parent[NPIX];
__device__ float2   g_acc[NPIX];               // (sum, cnt) at run starts
__device__ unsigned g_mask[WORDS];
__device__ int      g_roots[MAXR];
__device__ int      g_nroots;
__device__ double   g_total;
__device__ unsigned g_done;

// tanh for v > 0 via MUFU (verified rel_err 0.0 in rounds 5/7/9/11/12).
__device__ __forceinline__ float tanh_pos(float v) {
    float e = __expf(-2.0f * v);
    return __fdividef(1.0f - e, 1.0f + e);
}

// Path-halving find. Links always point to strictly smaller indices.
__device__ __forceinline__ int find_root(int i) {
    int p = g_parent[i];
    if (p == i) return i;
    while (true) {
        int gp = g_parent[p];
        if (gp == p) return p;
        g_parent[i] = gp;
        i = p; p = gp;
    }
}

__device__ __forceinline__ void unite(int a, int b) {
    int ra = find_root(a), rb = find_root(b);
    while (ra != rb) {
        if (ra > rb) { int t = ra; ra = rb; rb = t; }
        int old = atomicCAS(&g_parent[rb], rb, ra);
        if (old == rb) return;
        rb = find_root(old);
    }
}

// parent[i] = horizontal run start via warp max-scan over 128-pixel windows
// (windows never span rows). Emits the bitmask. At each run start
// (parent self), walks the run and plain-stores (tanh-sum, len) to g_acc.
__global__ void k_init(const float* __restrict__ x) {
    int chunk = blockIdx.x * blockDim.x + threadIdx.x;
    int base  = chunk << 2;
    float4 xv = reinterpret_cast<const float4*>(x)[chunk];
    float v[4] = {xv.x, xv.y, xv.z, xv.w};
    unsigned m = 0;
    #pragma unroll
    for (int j = 0; j < 4; j++) m |= (unsigned)(v[j] > 0.0f) << j;

    __shared__ unsigned char s_nib[256];
    s_nib[threadIdx.x] = (unsigned char)m;

    int lane  = threadIdx.x & 31;
    int wbase = base - (lane << 2);            // 128-aligned window base
    unsigned zeros = (~m) & 0xFu;
    int lz = zeros ? (base + 31 - __clz(zeros)) : (wbase - 1);

    int incl = lz;
    #pragma unroll
    for (int off = 1; off < 32; off <<= 1) {
        int t = __shfl_up_sync(0xffffffffu, incl, off);
        if (lane >= off) incl = max(incl, t);
    }
    int excl = __shfl_up_sync(0xffffffffu, incl, 1);
    if (lane == 0) excl = wbase - 1;

    int p[4];
    int prevz = excl;
    #pragma unroll
    for (int j = 0; j < 4; j++) {
        int i = base + j;
        if ((m >> j) & 1u) {
            int pj = prevz + 1;
            if (i == wbase && (i & (E - 1)) != 0 && x[i - 1] > 0.0f) pj = i - 1;
            p[j] = pj;
        } else {
            p[j] = i;
            prevz = i;
        }
    }
    if (m)   // all-negative chunks: parent entries are never read
        reinterpret_cast<int4*>(g_parent)[chunk] = make_int4(p[0], p[1], p[2], p[3]);

    // Per-run accumulation at run starts (p[j] == index itself).
    int colbase = base & (E - 1);
    #pragma unroll
    for (int j = 0; j < 4; j++) {
        int i = base + j;
        if (((m >> j) & 1u) && p[j] == i) {
            int   col = colbase + j;
            float s   = 0.0f;
            int   len = 0;
            float cur = v[j];
            while (true) {
                s += tanh_pos(cur);
                len++;
                if (col + len >= E) break;
                cur = (j + len < 4) ? v[j + len] : x[i + len];
                if (cur <= 0.0f) break;
            }
            g_acc[i] = make_float2(s, (float)len);   // plain store, single writer
        }
    }

    __syncthreads();
    if (threadIdx.x < 32) {
        unsigned w = 0;
        #pragma unroll
        for (int k = 0; k < 8; k++)
            w |= (unsigned)s_nib[threadIdx.x * 8 + k] << (4 * k);
        g_mask[blockIdx.x * 32 + threadIdx.x] = w;
    }
    if (chunk == 0) { g_total = 0.0; g_done = 0u; g_nroots = 0; }
}

// Vertical unions from mask words: one block per row (rows 1..E-1),
// one 32-pixel word per thread. Union once per overlap-run start.
__global__ void __launch_bounds__(WPR) k_merge() {
    int row  = blockIdx.x + 1;
    int wcol = threadIdx.x;
    int widx = row * WPR + wcol;
    unsigned wc = g_mask[widx];
    unsigned wu = g_mask[widx - WPR];
    unsigned ov = wc & wu;
    if (!ov) return;

    int lane = threadIdx.x & 31;
    unsigned cl = __shfl_up_sync(0xffffffffu, wc, 1);
    unsigned ul = __shfl_up_sync(0xffffffffu, wu, 1);
    unsigned carry = 0;
    if (wcol > 0) {
        if (lane == 0) {
            cl = g_mask[widx - 1];
            ul = g_mask[widx - 1 - WPR];
        }
        carry = (cl >> 31) & (ul >> 31) & 1u;
    }
    unsigned starts = ov & ~((ov << 1) | carry);

    int base = row * E + (wcol << 5);
    while (starts) {
        int b = __ffs(starts) - 1;
        starts &= starts - 1;
        unite(base + b, base + b - E);
    }
}

// One nibble (4 pixels) per thread, run starts from the mask. Roots go to a
// block-aggregated compact list; non-roots relocate their (s,len) to the root.
__global__ void __launch_bounds__(256) k_reloc() {
    __shared__ int sroots[512];
    __shared__ int s_cnt;
    __shared__ int s_base;
    if (threadIdx.x == 0) s_cnt = 0;
    __syncthreads();

    int nib   = blockIdx.x * blockDim.x + threadIdx.x;   // nibble index
    int widx  = nib >> 3;
    int sh    = (nib & 7) * 4;
    unsigned w = g_mask[widx];
    unsigned m = (w >> sh) & 0xFu;
    if (m) {
        unsigned carry;
        int base = nib << 2;
        if (sh)                      carry = (w >> (sh - 1)) & 1u;
        else if (base & (E - 1))     carry = g_mask[widx - 1] >> 31;
        else                         carry = 0u;
        unsigned starts = m & ~((m << 1) | carry) & 0xFu;

        float2* acc2 = reinterpret_cast<float2*>(g_acc);
        while (starts) {
            int b = __ffs(starts) - 1;
            starts &= starts - 1;
            int i = base + b;
            int p = g_parent[i];
            if (p == i) {
                sroots[atomicAdd(&s_cnt, 1)] = i;        // root
            } else {
                int r = find_root(i);
                float2 v = acc2[i];
                atomicAdd(acc2 + r, v);                  // sm_90+ vector red
            }
        }
    }
    __syncthreads();
    if (threadIdx.x == 0) s_base = atomicAdd(&g_nroots, s_cnt);
    __syncthreads();
    int n = s_cnt;
    for (int k = threadIdx.x; k < n; k += blockDim.x)
        g_roots[s_base + k] = sroots[k];
}

// Gather over the compact root list; ticketed final write.
__global__ void __launch_bounds__(256) k_final(float* __restrict__ out) {
    int n      = g_nroots;
    int stride = gridDim.x * blockDim.x;
    const float np1 = (float)(NPIX + 1);
    double t = 0.0;
    for (int k = blockIdx.x * blockDim.x + threadIdx.x; k < n; k += stride) {
        int    r = g_roots[k];
        float2 a = g_acc[r];
        t += (double)(a.x / (np1 - a.y));      // fp32 divide like reference
    }
    #pragma unroll
    for (int off = 16; off; off >>= 1)
        t += __shfl_down_sync(0xffffffffu, t, off);
    __shared__ double st[8];
    int lane = threadIdx.x & 31;
    int w    = threadIdx.x >> 5;
    if (lane == 0) st[w] = t;
    __syncthreads();
    if (w == 0) {
        int nw = blockDim.x >> 5;
        t = (lane < nw) ? st[lane] : 0.0;
        #pragma unroll
        for (int off = 4; off; off >>= 1)
            t += __shfl_down_sync(0xffffffffu, t, off);
        if (lane == 0) {
            atomicAdd(&g_total, t);
            __threadfence();
            unsigned ticket = atomicAdd(&g_done, 1u);
            if (ticket == gridDim.x - 1) {
                double tt = *((volatile double*)&g_total);
                out[0] = (n > 0) ? (float)(tt / (double)n) : 0.0f;
            }
        }
    }
}

extern "C" void kernel_launch(void* const* d_in, const int* in_sizes, int n_in,
                              void* d_out, int out_size) {
    const float* x   = (const float*)d_in[0];
    float*       out = (float*)d_out;

    const int threads = 256;
    const int chunks  = NPIX / 4;              // 4,194,304 nibbles/chunks

    k_init <<<chunks / threads, threads>>>(x);
    k_merge<<<E - 1, WPR>>>();
    k_reloc<<<chunks / threads, threads>>>();
    k_final<<<1024, threads>>>(out);
}

// round 14
// speedup vs baseline: 1.6283x; 1.0935x over previous
#include <cuda_runtime.h>

// LossMIDU: mean over 4-connected components of the tanh(x)>0 mask of
//   sum(tanh(x) in comp) / (N+1 - count(comp)).
// Flat run-based union-find CCL (round-9 structure) + compact root list:
//   k_init : parent[i] = horizontal run start (warp scan) + mask bits
//   k_merge: vertical CAS unions from mask words, one per overlap-run start
//   k_accum: one find + ONE float2 vector atomic per horizontal run;
//            component roots (parent==self) pushed to block-aggregated list
//   k_final: gather over compact root list, zero consumed entries, write out

static constexpr int E      = 4096;
static constexpr int NPIX   = E * E;
static constexpr int WORDS  = NPIX / 32;
static constexpr int WPR    = E / 32;          // mask words per row = 128
static constexpr int MAXR   = NPIX / 2;

__device__ int      g_parent[NPIX];
__device__ float2   g_acc[NPIX];               // (sum, cnt), written at roots only
__device__ unsigned g_mask[WORDS];
__device__ int      g_roots[MAXR];
__device__ int      g_nroots;
__device__ double   g_total;
__device__ unsigned g_done;

// tanh for v > 0 via MUFU (verified rel_err 0.0 in rounds 5/7/9/11/12/13).
__device__ __forceinline__ float tanh_pos(float v) {
    float e = __expf(-2.0f * v);
    return __fdividef(1.0f - e, 1.0f + e);
}

// Path-halving find. Links always point to strictly smaller indices.
__device__ __forceinline__ int find_root(int i) {
    int p = g_parent[i];
    if (p == i) return i;
    while (true) {
        int gp = g_parent[p];
        if (gp == p) return p;
        g_parent[i] = gp;   // path halving (monotone toward root, race-safe)
        i = p; p = gp;
    }
}

__device__ __forceinline__ void unite(int a, int b) {
    int ra = find_root(a), rb = find_root(b);
    while (ra != rb) {
        if (ra > rb) { int t = ra; ra = rb; rb = t; }
        int old = atomicCAS(&g_parent[rb], rb, ra);
        if (old == rb) return;
        rb = find_root(old);
    }
}

// parent[i] = horizontal run start via warp max-scan over 128-pixel windows
// (windows never span rows). Also emits the bitmask. Parent stores skipped
// for all-negative chunks (those entries are never read).
__global__ void k_init(const float* __restrict__ x) {
    int chunk = blockIdx.x * blockDim.x + threadIdx.x;
    int base  = chunk << 2;
    float4 xv = reinterpret_cast<const float4*>(x)[chunk];
    float v[4] = {xv.x, xv.y, xv.z, xv.w};
    unsigned m = 0;
    #pragma unroll
    for (int j = 0; j < 4; j++) m |= (unsigned)(v[j] > 0.0f) << j;

    __shared__ unsigned char s_nib[256];
    s_nib[threadIdx.x] = (unsigned char)m;

    int lane  = threadIdx.x & 31;
    int wbase = base - (lane << 2);            // 128-aligned window base
    unsigned zeros = (~m) & 0xFu;
    int lz = zeros ? (base + 31 - __clz(zeros)) : (wbase - 1);

    int incl = lz;
    #pragma unroll
    for (int off = 1; off < 32; off <<= 1) {
        int t = __shfl_up_sync(0xffffffffu, incl, off);
        if (lane >= off) incl = max(incl, t);
    }
    int excl = __shfl_up_sync(0xffffffffu, incl, 1);
    if (lane == 0) excl = wbase - 1;

    int p[4];
    int prevz = excl;
    #pragma unroll
    for (int j = 0; j < 4; j++) {
        int i = base + j;
        if ((m >> j) & 1u) {
            int pj = prevz + 1;
            if (i == wbase && (i & (E - 1)) != 0 && x[i - 1] > 0.0f) pj = i - 1;
            p[j] = pj;
        } else {
            p[j] = i;
            prevz = i;
        }
    }
    if (m)
        reinterpret_cast<int4*>(g_parent)[chunk] = make_int4(p[0], p[1], p[2], p[3]);

    __syncthreads();
    if (threadIdx.x < 32) {
        unsigned w = 0;
        #pragma unroll
        for (int k = 0; k < 8; k++)
            w |= (unsigned)s_nib[threadIdx.x * 8 + k] << (4 * k);
        g_mask[blockIdx.x * 32 + threadIdx.x] = w;
    }
    if (chunk == 0) { g_total = 0.0; g_done = 0u; g_nroots = 0; }
}

// Vertical unions from mask words: one block per row (rows 1..E-1),
// one 32-pixel word per thread. Union once per overlap-run start.
__global__ void __launch_bounds__(WPR) k_merge() {
    int row  = blockIdx.x + 1;
    int wcol = threadIdx.x;
    int widx = row * WPR + wcol;
    unsigned wc = g_mask[widx];
    unsigned wu = g_mask[widx - WPR];
    unsigned ov = wc & wu;
    if (!ov) return;

    int lane = threadIdx.x & 31;
    unsigned cl = __shfl_up_sync(0xffffffffu, wc, 1);
    unsigned ul = __shfl_up_sync(0xffffffffu, wu, 1);
    unsigned carry = 0;
    if (wcol > 0) {
        if (lane == 0) {
            cl = g_mask[widx - 1];
            ul = g_mask[widx - 1 - WPR];
        }
        carry = (cl >> 31) & (ul >> 31) & 1u;
    }
    unsigned starts = ov & ~((ov << 1) | carry);

    int base = row * E + (wcol << 5);
    while (starts) {
        int b = __ffs(starts) - 1;
        starts &= starts - 1;
        unite(base + b, base + b - E);
    }
}

// One find + one float2 vector atomic per horizontal run. Component roots
// (first parent load == self) are pushed to a block-aggregated compact list.
__global__ void __launch_bounds__(256) k_accum(const float* __restrict__ x) {
    __shared__ int sroots[512];                 // max run starts in 1024 pixels
    __shared__ int s_cnt;
    __shared__ int s_base;
    if (threadIdx.x == 0) s_cnt = 0;
    __syncthreads();

    int chunk = blockIdx.x * blockDim.x + threadIdx.x;
    int base  = chunk << 2;
    float4 xv = reinterpret_cast<const float4*>(x)[chunk];
    float v[4] = {xv.x, xv.y, xv.z, xv.w};
    int lane    = threadIdx.x & 31;
    float lw    = __shfl_up_sync(0xffffffffu, xv.w, 1);
    int colbase = base & (E - 1);
    float left0;
    if (colbase == 0)   left0 = -1.0f;
    else if (lane > 0)  left0 = lw;
    else                left0 = x[base - 1];

    #pragma unroll
    for (int j = 0; j < 4; j++) {
        float lv = j ? v[j-1] : left0;
        if (v[j] > 0.0f && lv <= 0.0f) {
            int   i   = base + j;
            int   col = colbase + j;
            float s   = 0.0f;
            int   len = 0;
            float cur = v[j];
            while (true) {
                s += tanh_pos(cur);
                len++;
                if (col + len >= E) break;
                cur = (j + len < 4) ? v[j + len] : x[i + len];
                if (cur <= 0.0f) break;
            }
            int p = g_parent[i];
            int r;
            if (p == i) {
                r = i;                                    // component root
                sroots[atomicAdd(&s_cnt, 1)] = i;
            } else {
                r = find_root(i);
            }
            atomicAdd(&g_acc[r], make_float2(s, (float)len));  // sm_90+ vector red
        }
    }

    __syncthreads();
    if (threadIdx.x == 0) s_base = atomicAdd(&g_nroots, s_cnt);
    __syncthreads();
    int n = s_cnt;
    for (int k = threadIdx.x; k < n; k += blockDim.x)
        g_roots[s_base + k] = sroots[k];
}

// Gather over the compact root list; zero consumed entries (lazy re-init for
// the next replay — only roots are ever atomically written); ticketed output.
__global__ void __launch_bounds__(256) k_final(float* __restrict__ out) {
    int n      = g_nroots;
    int stride = gridDim.x * blockDim.x;
    const float np1 = (float)(NPIX + 1);
    double t = 0.0;
    for (int k = blockIdx.x * blockDim.x + threadIdx.x; k < n; k += stride) {
        int    r = g_roots[k];
        float2 a = g_acc[r];
        t += (double)(a.x / (np1 - a.y));      // fp32 divide like reference
        g_acc[r] = make_float2(0.f, 0.f);
    }
    #pragma unroll
    for (int off = 16; off; off >>= 1)
        t += __shfl_down_sync(0xffffffffu, t, off);
    __shared__ double st[8];
    int lane = threadIdx.x & 31;
    int w    = threadIdx.x >> 5;
    if (lane == 0) st[w] = t;
    __syncthreads();
    if (w == 0) {
        int nw = blockDim.x >> 5;
        t = (lane < nw) ? st[lane] : 0.0;
        #pragma unroll
        for (int off = 4; off; off >>= 1)
            t += __shfl_down_sync(0xffffffffu, t, off);
        if (lane == 0) {
            atomicAdd(&g_total, t);
            __threadfence();
            unsigned ticket = atomicAdd(&g_done, 1u);
            if (ticket == gridDim.x - 1) {
                double tt = *((volatile double*)&g_total);
                out[0] = (n > 0) ? (float)(tt / (double)n) : 0.0f;
            }
        }
    }
}

extern "C" void kernel_launch(void* const* d_in, const int* in_sizes, int n_in,
                              void* d_out, int out_size) {
    const float* x   = (const float*)d_in[0];
    float*       out = (float*)d_out;

    const int threads = 256;
    const int chunks  = NPIX / 4;

    k_init <<<chunks / threads, threads>>>(x);
    k_merge<<<E - 1, WPR>>>();
    k_accum<<<chunks / threads, threads>>>(x);
    k_final<<<1024, threads>>>(out);
}